// round 5
// baseline (speedup 1.0000x reference)
#include <cuda_runtime.h>
#include <cuda_fp16.h>
#include <cstdint>

// Problem constants (fixed by the dataset)
#define N_MAX   100000
#define E_MAX   1600000
#define ROW     128        // xl(64) | xr(64) halves per node
#define HC      64         // HEADS * OUT_CH
#define OUTC    32

// -------- scratch (static device globals; no allocation) --------
__device__ __align__(128) __half g_xlr[(size_t)N_MAX * ROW];    // 25.6 MB (fp16)
__device__ __align__(128) int   g_deg[N_MAX];
__device__ __align__(128) int   g_off[N_MAX + 1];
__device__ __align__(128) int   g_cur[N_MAX];
__device__ __align__(128) int   g_src[E_MAX];
__device__ int g_is64;   // 1 if edge_index is int64, 0 if int32

// ---------------- helpers ----------------
__device__ __forceinline__ unsigned long long pack_dup(float a) {
    unsigned int au = __float_as_uint(a);
    unsigned long long r;
    asm("mov.b64 %0, {%1, %1};" : "=l"(r) : "r"(au));
    return r;
}
__device__ __forceinline__ void unpack2(unsigned long long v, float& lo, float& hi) {
    unsigned int l, h;
    asm("mov.b64 {%0, %1}, %2;" : "=r"(l), "=r"(h) : "l"(v));
    lo = __uint_as_float(l); hi = __uint_as_float(h);
}
__device__ __forceinline__ void fma2(unsigned long long& acc, unsigned long long a, unsigned long long b) {
    asm("fma.rn.f32x2 %0, %1, %2, %0;" : "+l"(acc) : "l"(a), "l"(b));
}
__device__ __forceinline__ float lrelu(float x) { return (x > 0.f) ? x : 0.2f * x; }

__device__ __forceinline__ void load_edge(const void* ei, int E, int ec, int& j, int& i) {
    if (g_is64) {
        const long long* p = (const long long*)ei;
        j = (int)p[ec]; i = (int)p[(size_t)E + ec];
    } else {
        const int* p = (const int*)ei;
        j = p[ec]; i = p[(size_t)E + ec];
    }
}

// ---------------- kernel D: detect edge_index dtype ----------------
__global__ void k_detect(const void* ei, int N) {
    const long long* p = (const long long*)ei;
    int ok = 1;
    #pragma unroll 1
    for (int t = 0; t < 64; t++) {
        long long v = p[t];
        if (v < 0 || v >= (long long)N) { ok = 0; break; }
    }
    g_is64 = ok;
}

// ---------------- CSR build ----------------
__global__ void k_zero_deg(int N) {
    int idx = blockIdx.x * blockDim.x + threadIdx.x;
    if (idx < N) g_deg[idx] = 0;
}

__global__ void k_hist(const void* __restrict__ ei, int E, int N) {
    int e = blockIdx.x * blockDim.x + threadIdx.x;
    if (e >= E) return;
    int j, i;
    load_edge(ei, E, e, j, i);
    atomicAdd(&g_deg[i], 1);
}

// single-block exclusive scan over g_deg -> g_off/g_cur (4 elems/thread/iter)
__global__ void __launch_bounds__(1024) k_scan(int N) {
    __shared__ int warp_tot[32];
    __shared__ int s_carry;
    const int tid = threadIdx.x, lane = tid & 31, wid = tid >> 5;
    if (tid == 0) s_carry = 0;
    __syncthreads();
    for (int base = 0; base < N; base += 4096) {
        int idx = base + tid * 4;
        int4 v = make_int4(0, 0, 0, 0);
        if (idx + 3 < N) v = *reinterpret_cast<const int4*>(&g_deg[idx]);
        else {
            if (idx     < N) v.x = g_deg[idx];
            if (idx + 1 < N) v.y = g_deg[idx + 1];
            if (idx + 2 < N) v.z = g_deg[idx + 2];
        }
        int tsum = v.x + v.y + v.z + v.w;
        int s = tsum;
        #pragma unroll
        for (int m = 1; m < 32; m <<= 1) {
            int o = __shfl_up_sync(0xffffffffu, s, m);
            if (lane >= m) s += o;
        }
        if (lane == 31) warp_tot[wid] = s;
        __syncthreads();
        if (wid == 0) {
            int w = warp_tot[lane];
            int ws = w;
            #pragma unroll
            for (int m = 1; m < 32; m <<= 1) {
                int o = __shfl_up_sync(0xffffffffu, ws, m);
                if (lane >= m) ws += o;
            }
            warp_tot[lane] = ws - w;   // exclusive
        }
        __syncthreads();
        int excl = (s - tsum) + warp_tot[wid] + s_carry;
        if (idx     < N) { g_off[idx]     = excl;             g_cur[idx]     = excl; }
        if (idx + 1 < N) { int e1 = excl + v.x;               g_off[idx + 1] = e1; g_cur[idx + 1] = e1; }
        if (idx + 2 < N) { int e2 = excl + v.x + v.y;         g_off[idx + 2] = e2; g_cur[idx + 2] = e2; }
        if (idx + 3 < N) { int e3 = excl + v.x + v.y + v.z;   g_off[idx + 3] = e3; g_cur[idx + 3] = e3; }
        __syncthreads();                 // everyone done with old s_carry
        if (tid == 1023) s_carry = excl + tsum;   // = old carry + block total
        __syncthreads();
    }
    if (threadIdx.x == 0) g_off[N] = s_carry;
}

__global__ void k_scatter(const void* __restrict__ ei, int E, int N) {
    int e = blockIdx.x * blockDim.x + threadIdx.x;
    if (e >= E) return;
    int j, i;
    load_edge(ei, E, e, j, i);
    int pos = atomicAdd(&g_cur[i], 1);
    g_src[pos] = j;
}

// ---------------- kernel 1: xlr = fp16( x @ [Wl|Wr] + [bl|br] ) ----------------
// BM=64 rows, BN=128 cols, BK=32.  256 threads, f32x2 packed FMA.
__global__ void __launch_bounds__(256) k_gemm(
    const float* __restrict__ x, const float* __restrict__ Wl,
    const float* __restrict__ bl, const float* __restrict__ Wr,
    const float* __restrict__ br, int N)
{
    __shared__ __align__(16) float Xs_t[32][66];   // [kk][m]
    __shared__ __align__(16) float Ws[32][128];    // [kk][n]

    const int tid = threadIdx.x;
    const int tx = tid & 31;
    const int ty = tid >> 5;
    const int m0 = ty * 8;
    const int blockM = blockIdx.x * 64;

    unsigned long long acc[4][4];
    #pragma unroll
    for (int a = 0; a < 4; a++)
        #pragma unroll
        for (int b = 0; b < 4; b++) acc[a][b] = 0ull;

    for (int k0 = 0; k0 < 128; k0 += 32) {
        #pragma unroll
        for (int it = 0; it < 2; it++) {
            int t = tid + it * 256;          // 0..511
            int m = t >> 3;                  // 0..63
            int kkv = (t & 7) * 4;
            int gm = blockM + m;
            float4 v = make_float4(0.f, 0.f, 0.f, 0.f);
            if (gm < N) v = *reinterpret_cast<const float4*>(&x[(size_t)gm * 128 + k0 + kkv]);
            Xs_t[kkv + 0][m] = v.x;
            Xs_t[kkv + 1][m] = v.y;
            Xs_t[kkv + 2][m] = v.z;
            Xs_t[kkv + 3][m] = v.w;
        }
        #pragma unroll
        for (int it = 0; it < 4; it++) {
            int t = tid + it * 256;          // 0..1023
            int kk = t >> 5;                 // 0..31
            int n  = (t & 31) * 4;
            int gk = k0 + kk;
            float4 v = (n < 64)
                ? *reinterpret_cast<const float4*>(&Wl[(size_t)gk * 64 + n])
                : *reinterpret_cast<const float4*>(&Wr[(size_t)gk * 64 + (n - 64)]);
            *reinterpret_cast<float4*>(&Ws[kk][n]) = v;
        }
        __syncthreads();

        #pragma unroll
        for (int kk = 0; kk < 32; kk++) {
            unsigned long long apair[4];
            #pragma unroll
            for (int rp = 0; rp < 4; rp++)
                apair[rp] = *reinterpret_cast<const unsigned long long*>(&Xs_t[kk][m0 + 2 * rp]);
            #pragma unroll
            for (int jj = 0; jj < 4; jj++) {
                unsigned long long wp = pack_dup(Ws[kk][tx + 32 * jj]);
                #pragma unroll
                for (int rp = 0; rp < 4; rp++)
                    fma2(acc[rp][jj], apair[rp], wp);
            }
        }
        __syncthreads();
    }

    #pragma unroll
    for (int jj = 0; jj < 4; jj++) {
        int col = tx + 32 * jj;
        float bsum = (col < HC) ? bl[col] : br[col - HC];
        #pragma unroll
        for (int rp = 0; rp < 4; rp++) {
            float lo, hi;
            unpack2(acc[rp][jj], lo, hi);
            int gm = blockM + m0 + 2 * rp;
            if (gm < N)     g_xlr[(size_t)gm * ROW + col]       = __float2half_rn(lo + bsum);
            if (gm + 1 < N) g_xlr[(size_t)(gm + 1) * ROW + col] = __float2half_rn(hi + bsum);
        }
    }
}

// ---------------- kernel 2: per-node aggregation (warp per dst node) ----------------
// Lane k holds channels (2k, 2k+1) of the 64-wide [head0|head1] vector.
// Lanes 0-15 = head 0, lanes 16-31 = head 1.
__global__ void __launch_bounds__(256) k_agg(
    const float* __restrict__ att, const float* __restrict__ bias,
    float* __restrict__ out, int N)
{
    const int warp = (blockIdx.x * 256 + threadIdx.x) >> 5;
    const int lane = threadIdx.x & 31;
    if (warp >= N) return;
    const int i = warp;

    // xr[i] for this lane (2 channels)
    __half2 xr2 = *reinterpret_cast<const __half2*>(g_xlr + (size_t)i * ROW + HC + 2 * lane);
    float2 b = __half22float2(xr2);
    float2 t = *reinterpret_cast<const float2*>(&att[2 * lane]);

    float2 acc = make_float2(0.f, 0.f);
    float d = 0.f;

    const int off = g_off[i];
    const int deg = g_deg[i];

    // --- process one edge given its preloaded xl half2 ---
    auto process = [&](__half2 xl2) {
        float2 a = __half22float2(xl2);
        float s = t.x * lrelu(a.x + b.x) + t.y * lrelu(a.y + b.y);
        #pragma unroll
        for (int m = 1; m < 16; m <<= 1) s += __shfl_xor_sync(0xffffffffu, s, m);
        float p = __expf(s) ; // see note below
        acc.x += p * a.x;
        acc.y += p * a.y;
        d += p;
    };

    // self loop first (xl[i])
    {
        __half2 v = *reinterpret_cast<const __half2*>(g_xlr + (size_t)i * ROW + 2 * lane);
        process(v);
    }

    // CSR edges, batched index loads + 1-deep prefetch pipeline
    for (int tb = 0; tb < deg; tb += 32) {
        int cnt = deg - tb; if (cnt > 32) cnt = 32;
        int myidx = tb + lane;
        int mysrc = (myidx < deg) ? g_src[off + myidx] : 0;

        int j0 = __shfl_sync(0xffffffffu, mysrc, 0);
        __half2 vcur = *reinterpret_cast<const __half2*>(g_xlr + (size_t)j0 * ROW + 2 * lane);
        for (int u = 0; u < cnt; u++) {
            __half2 vnext = vcur;
            if (u + 1 < cnt) {
                int jn = __shfl_sync(0xffffffffu, mysrc, u + 1);
                vnext = *reinterpret_cast<const __half2*>(g_xlr + (size_t)jn * ROW + 2 * lane);
            }
            process(vcur);
            vcur = vnext;
        }
    }

    // epilogue: normalize, head-mean, bias, silu, write
    float invd = 1.f / (d + 1e-16f);
    float2 v; v.x = acc.x * invd; v.y = acc.y * invd;
    float ox = __shfl_xor_sync(0xffffffffu, v.x, 16);
    float oy = __shfl_xor_sync(0xffffffffu, v.y, 16);
    if (lane < 16) {
        float r0 = 0.5f * (v.x + ox) + bias[2 * lane];
        float r1 = 0.5f * (v.y + oy) + bias[2 * lane + 1];
        r0 = r0 / (1.f + expf(-r0));
        r1 = r1 / (1.f + expf(-r1));
        *reinterpret_cast<float2*>(&out[(size_t)i * OUTC + 2 * lane]) = make_float2(r0, r1);
    }
}

// ---------------- launch ----------------
extern "C" void kernel_launch(void* const* d_in, const int* in_sizes, int n_in,
                              void* d_out, int out_size) {
    const float* x    = (const float*)d_in[0];
    const float* Wl   = (const float*)d_in[1];
    const float* bl   = (const float*)d_in[2];
    const float* Wr   = (const float*)d_in[3];
    const float* br   = (const float*)d_in[4];
    const float* att  = (const float*)d_in[5];
    const float* bias = (const float*)d_in[6];
    const void*  ei   = (const void*)d_in[7];
    float* out = (float*)d_out;

    int N = in_sizes[0] / 128;   // 100000
    int E = in_sizes[7] / 2;     // 1600000

    k_detect<<<1, 1>>>(ei, N);
    k_zero_deg<<<(N + 255) / 256, 256>>>(N);
    k_hist<<<(E + 255) / 256, 256>>>(ei, E, N);
    k_scan<<<1, 1024>>>(N);
    k_scatter<<<(E + 255) / 256, 256>>>(ei, E, N);
    k_gemm<<<(N + 63) / 64, 256>>>(x, Wl, bl, Wr, br, N);
    k_agg<<<(N * 32 + 255) / 256, 256>>>(att, bias, out, N);
}

// round 8
// speedup vs baseline: 1.2963x; 1.2963x over previous
#include <cuda_runtime.h>
#include <cuda_fp16.h>
#include <cstdint>

// Problem constants (fixed by the dataset)
#define N_MAX   100000
#define E_MAX   1600000
#define ROW     128        // xl(64) | xr(64) halves per node
#define HC      64         // HEADS * OUT_CH
#define OUTC    32
#define SCAN_BS 1024
#define NBLK_MAX ((N_MAX + SCAN_BS - 1) / SCAN_BS)   // 98

// -------- scratch (static device globals; no allocation) --------
__device__ __align__(128) __half g_xlr[(size_t)N_MAX * ROW];    // 25.6 MB (fp16)
__device__ __align__(128) int   g_deg[N_MAX];
__device__ __align__(128) int   g_off[N_MAX + 1];
__device__ __align__(128) int   g_cur[N_MAX];
__device__ __align__(128) int   g_src[E_MAX];
__device__ __align__(128) int   g_blk[NBLK_MAX + 1];
__device__ int g_is64;   // 1 if edge_index is int64, 0 if int32

// ---------------- helpers ----------------
__device__ __forceinline__ unsigned long long pack_dup(float a) {
    unsigned int au = __float_as_uint(a);
    unsigned long long r;
    asm("mov.b64 %0, {%1, %1};" : "=l"(r) : "r"(au));
    return r;
}
__device__ __forceinline__ void unpack2(unsigned long long v, float& lo, float& hi) {
    unsigned int l, h;
    asm("mov.b64 {%0, %1}, %2;" : "=r"(l), "=r"(h) : "l"(v));
    lo = __uint_as_float(l); hi = __uint_as_float(h);
}
__device__ __forceinline__ void fma2(unsigned long long& acc, unsigned long long a, unsigned long long b) {
    asm("fma.rn.f32x2 %0, %1, %2, %0;" : "+l"(acc) : "l"(a), "l"(b));
}
__device__ __forceinline__ float lrelu(float x) { return (x > 0.f) ? x : 0.2f * x; }

__device__ __forceinline__ void load_edge(const void* ei, int E, int ec, int& j, int& i) {
    if (g_is64) {
        const long long* p = (const long long*)ei;
        j = (int)p[ec]; i = (int)p[(size_t)E + ec];
    } else {
        const int* p = (const int*)ei;
        j = p[ec]; i = p[(size_t)E + ec];
    }
}

// ---------------- kernel D: detect edge_index dtype ----------------
__global__ void k_detect(const void* ei, int N) {
    const long long* p = (const long long*)ei;
    int ok = 1;
    #pragma unroll 1
    for (int t = 0; t < 64; t++) {
        long long v = p[t];
        if (v < 0 || v >= (long long)N) { ok = 0; break; }
    }
    g_is64 = ok;
}

// ---------------- CSR build ----------------
__global__ void k_zero_deg(int N) {
    int idx = blockIdx.x * blockDim.x + threadIdx.x;
    if (idx < N) g_deg[idx] = 0;
}

__global__ void k_hist(const void* __restrict__ ei, int E, int N) {
    int e = blockIdx.x * blockDim.x + threadIdx.x;
    if (e >= E) return;
    int j, i;
    load_edge(ei, E, e, j, i);
    atomicAdd(&g_deg[i], 1);
}

// --- two-level exclusive scan ---
// kA: per-block local exclusive scan of g_deg -> g_off (local), block totals -> g_blk
__global__ void __launch_bounds__(SCAN_BS) kA_scan_local(int N) {
    __shared__ int wt[SCAN_BS / 32];
    const int tid = threadIdx.x, lane = tid & 31, wid = tid >> 5;
    int idx = blockIdx.x * SCAN_BS + tid;
    int v = (idx < N) ? g_deg[idx] : 0;
    int s = v;
    #pragma unroll
    for (int m = 1; m < 32; m <<= 1) {
        int o = __shfl_up_sync(0xffffffffu, s, m);
        if (lane >= m) s += o;
    }
    if (lane == 31) wt[wid] = s;
    __syncthreads();
    if (wid == 0) {
        int w = wt[lane];
        int ws = w;
        #pragma unroll
        for (int m = 1; m < 32; m <<= 1) {
            int o = __shfl_up_sync(0xffffffffu, ws, m);
            if (lane >= m) ws += o;
        }
        wt[lane] = ws - w;   // exclusive warp offsets
    }
    __syncthreads();
    int excl = (s - v) + wt[wid];
    if (idx < N) g_off[idx] = excl;
    if (tid == SCAN_BS - 1) g_blk[blockIdx.x] = excl + v;   // block total
}

// kB: single small block scans the (<=128) block totals exclusively, writes grand total
__global__ void __launch_bounds__(128) kB_scan_blk(int NB, int N) {
    __shared__ int wt[4];
    const int tid = threadIdx.x, lane = tid & 31, wid = tid >> 5;
    int v = (tid < NB) ? g_blk[tid] : 0;
    int s = v;
    #pragma unroll
    for (int m = 1; m < 32; m <<= 1) {
        int o = __shfl_up_sync(0xffffffffu, s, m);
        if (lane >= m) s += o;
    }
    if (lane == 31) wt[wid] = s;
    __syncthreads();
    if (tid == 0) {
        int c = 0;
        #pragma unroll
        for (int q = 0; q < 4; q++) { int t = wt[q]; wt[q] = c; c += t; }
    }
    __syncthreads();
    int excl = (s - v) + wt[wid];
    if (tid < NB) g_blk[tid] = excl;
    if (tid == NB - 1) g_off[N] = excl + v;   // grand total (=E)
}

// kC: add block offsets; init g_cur
__global__ void kC_add(int N) {
    int idx = blockIdx.x * blockDim.x + threadIdx.x;
    if (idx < N) {
        int o = g_off[idx] + g_blk[idx >> 10];
        g_off[idx] = o;
        g_cur[idx] = o;
    }
}

__global__ void k_scatter(const void* __restrict__ ei, int E, int N) {
    int e = blockIdx.x * blockDim.x + threadIdx.x;
    if (e >= E) return;
    int j, i;
    load_edge(ei, E, e, j, i);
    int pos = atomicAdd(&g_cur[i], 1);
    g_src[pos] = j;
}

// ---------------- kernel 1: xlr = fp16( x @ [Wl|Wr] + [bl|br] ) ----------------
// BM=64 rows, BN=128 cols, BK=32.  256 threads, f32x2 packed FMA.
__global__ void __launch_bounds__(256) k_gemm(
    const float* __restrict__ x, const float* __restrict__ Wl,
    const float* __restrict__ bl, const float* __restrict__ Wr,
    const float* __restrict__ br, int N)
{
    __shared__ __align__(16) float Xs_t[32][66];   // [kk][m]
    __shared__ __align__(16) float Ws[32][128];    // [kk][n]

    const int tid = threadIdx.x;
    const int tx = tid & 31;
    const int ty = tid >> 5;
    const int m0 = ty * 8;
    const int blockM = blockIdx.x * 64;

    unsigned long long acc[4][4];
    #pragma unroll
    for (int a = 0; a < 4; a++)
        #pragma unroll
        for (int b = 0; b < 4; b++) acc[a][b] = 0ull;

    for (int k0 = 0; k0 < 128; k0 += 32) {
        #pragma unroll
        for (int it = 0; it < 2; it++) {
            int t = tid + it * 256;          // 0..511
            int m = t >> 3;                  // 0..63
            int kkv = (t & 7) * 4;
            int gm = blockM + m;
            float4 v = make_float4(0.f, 0.f, 0.f, 0.f);
            if (gm < N) v = *reinterpret_cast<const float4*>(&x[(size_t)gm * 128 + k0 + kkv]);
            Xs_t[kkv + 0][m] = v.x;
            Xs_t[kkv + 1][m] = v.y;
            Xs_t[kkv + 2][m] = v.z;
            Xs_t[kkv + 3][m] = v.w;
        }
        #pragma unroll
        for (int it = 0; it < 4; it++) {
            int t = tid + it * 256;          // 0..1023
            int kk = t >> 5;                 // 0..31
            int n  = (t & 31) * 4;
            int gk = k0 + kk;
            float4 v = (n < 64)
                ? *reinterpret_cast<const float4*>(&Wl[(size_t)gk * 64 + n])
                : *reinterpret_cast<const float4*>(&Wr[(size_t)gk * 64 + (n - 64)]);
            *reinterpret_cast<float4*>(&Ws[kk][n]) = v;
        }
        __syncthreads();

        #pragma unroll
        for (int kk = 0; kk < 32; kk++) {
            unsigned long long apair[4];
            #pragma unroll
            for (int rp = 0; rp < 4; rp++)
                apair[rp] = *reinterpret_cast<const unsigned long long*>(&Xs_t[kk][m0 + 2 * rp]);
            #pragma unroll
            for (int jj = 0; jj < 4; jj++) {
                unsigned long long wp = pack_dup(Ws[kk][tx + 32 * jj]);
                #pragma unroll
                for (int rp = 0; rp < 4; rp++)
                    fma2(acc[rp][jj], apair[rp], wp);
            }
        }
        __syncthreads();
    }

    #pragma unroll
    for (int jj = 0; jj < 4; jj++) {
        int col = tx + 32 * jj;
        float bsum = (col < HC) ? bl[col] : br[col - HC];
        #pragma unroll
        for (int rp = 0; rp < 4; rp++) {
            float lo, hi;
            unpack2(acc[rp][jj], lo, hi);
            int gm = blockM + m0 + 2 * rp;
            if (gm < N)     g_xlr[(size_t)gm * ROW + col]       = __float2half_rn(lo + bsum);
            if (gm + 1 < N) g_xlr[(size_t)(gm + 1) * ROW + col] = __float2half_rn(hi + bsum);
        }
    }
}

// ---------------- kernel 2: per-node aggregation (warp per dst node) ----------------
// Lane k holds channels (2k, 2k+1); lanes 0-15 = head 0, 16-31 = head 1.
__global__ void __launch_bounds__(256) k_agg(
    const float* __restrict__ att, const float* __restrict__ bias,
    float* __restrict__ out, int N)
{
    const int warp = (blockIdx.x * 256 + threadIdx.x) >> 5;
    const int lane = threadIdx.x & 31;
    if (warp >= N) return;
    const int i = warp;

    __half2 xr2 = *reinterpret_cast<const __half2*>(g_xlr + (size_t)i * ROW + HC + 2 * lane);
    float2 b = __half22float2(xr2);
    float2 t = *reinterpret_cast<const float2*>(&att[2 * lane]);

    float2 acc = make_float2(0.f, 0.f);
    float d = 0.f;

    const int off = g_off[i];
    const int deg = g_deg[i];

    auto process = [&](__half2 xl2) {
        float2 a = __half22float2(xl2);
        float s = t.x * lrelu(a.x + b.x) + t.y * lrelu(a.y + b.y);
        #pragma unroll
        for (int m = 1; m < 16; m <<= 1) s += __shfl_xor_sync(0xffffffffu, s, m);
        float p = __expf(s);
        acc.x += p * a.x;
        acc.y += p * a.y;
        d += p;
    };

    // self loop first (xl[i])
    {
        __half2 v = *reinterpret_cast<const __half2*>(g_xlr + (size_t)i * ROW + 2 * lane);
        process(v);
    }

    // CSR edges, batched index loads + 1-deep prefetch pipeline
    for (int tb = 0; tb < deg; tb += 32) {
        int cnt = deg - tb; if (cnt > 32) cnt = 32;
        int myidx = tb + lane;
        int mysrc = (myidx < deg) ? g_src[off + myidx] : 0;

        int j0 = __shfl_sync(0xffffffffu, mysrc, 0);
        __half2 vcur = *reinterpret_cast<const __half2*>(g_xlr + (size_t)j0 * ROW + 2 * lane);
        for (int u = 0; u < cnt; u++) {
            __half2 vnext = vcur;
            if (u + 1 < cnt) {
                int jn = __shfl_sync(0xffffffffu, mysrc, u + 1);
                vnext = *reinterpret_cast<const __half2*>(g_xlr + (size_t)jn * ROW + 2 * lane);
            }
            process(vcur);
            vcur = vnext;
        }
    }

    // epilogue: normalize, head-mean, bias, silu, write
    float invd = 1.f / (d + 1e-16f);
    float2 v; v.x = acc.x * invd; v.y = acc.y * invd;
    float ox = __shfl_xor_sync(0xffffffffu, v.x, 16);
    float oy = __shfl_xor_sync(0xffffffffu, v.y, 16);
    if (lane < 16) {
        float r0 = 0.5f * (v.x + ox) + bias[2 * lane];
        float r1 = 0.5f * (v.y + oy) + bias[2 * lane + 1];
        r0 = r0 / (1.f + expf(-r0));
        r1 = r1 / (1.f + expf(-r1));
        *reinterpret_cast<float2*>(&out[(size_t)i * OUTC + 2 * lane]) = make_float2(r0, r1);
    }
}

// ---------------- launch ----------------
extern "C" void kernel_launch(void* const* d_in, const int* in_sizes, int n_in,
                              void* d_out, int out_size) {
    const float* x    = (const float*)d_in[0];
    const float* Wl   = (const float*)d_in[1];
    const float* bl   = (const float*)d_in[2];
    const float* Wr   = (const float*)d_in[3];
    const float* br   = (const float*)d_in[4];
    const float* att  = (const float*)d_in[5];
    const float* bias = (const float*)d_in[6];
    const void*  ei   = (const void*)d_in[7];
    float* out = (float*)d_out;

    int N = in_sizes[0] / 128;   // 100000
    int E = in_sizes[7] / 2;     // 1600000
    int NB = (N + SCAN_BS - 1) / SCAN_BS;

    k_detect<<<1, 1>>>(ei, N);
    k_zero_deg<<<(N + 255) / 256, 256>>>(N);
    k_hist<<<(E + 255) / 256, 256>>>(ei, E, N);
    kA_scan_local<<<NB, SCAN_BS>>>(N);
    kB_scan_blk<<<1, 128>>>(NB, N);
    kC_add<<<(N + 255) / 256, 256>>>(N);
    k_scatter<<<(E + 255) / 256, 256>>>(ei, E, N);
    k_gemm<<<(N + 63) / 64, 256>>>(x, Wl, bl, Wr, br, N);
    k_agg<<<(N * 32 + 255) / 256, 256>>>(att, bias, out, N);
}

// round 9
// speedup vs baseline: 1.3393x; 1.0332x over previous
#include <cuda_runtime.h>
#include <cuda_fp16.h>
#include <cstdint>

// Problem constants (fixed by the dataset)
#define N_MAX   100000
#define E_MAX   1600000
#define ROW     128        // xl(64) | xr(64) halves per node
#define HC      64         // HEADS * OUT_CH
#define OUTC    32
#define SCAN_BS 1024
#define NBLK_MAX ((N_MAX + SCAN_BS - 1) / SCAN_BS)   // 98

// -------- scratch (static device globals; no allocation) --------
__device__ __align__(128) __half g_xlr[(size_t)N_MAX * ROW];    // 25.6 MB (fp16)
__device__ __align__(128) int   g_deg[N_MAX];
__device__ __align__(128) int   g_off[N_MAX + 1];
__device__ __align__(128) int   g_cur[N_MAX];
__device__ __align__(128) int   g_src[E_MAX];
__device__ __align__(128) int   g_blk[NBLK_MAX + 1];
__device__ int g_is64;   // 1 if edge_index is int64, 0 if int32

// ---------------- helpers ----------------
__device__ __forceinline__ unsigned long long pack_dup(float a) {
    unsigned int au = __float_as_uint(a);
    unsigned long long r;
    asm("mov.b64 %0, {%1, %1};" : "=l"(r) : "r"(au));
    return r;
}
__device__ __forceinline__ void unpack2(unsigned long long v, float& lo, float& hi) {
    unsigned int l, h;
    asm("mov.b64 {%0, %1}, %2;" : "=r"(l), "=r"(h) : "l"(v));
    lo = __uint_as_float(l); hi = __uint_as_float(h);
}
__device__ __forceinline__ void fma2(unsigned long long& acc, unsigned long long a, unsigned long long b) {
    asm("fma.rn.f32x2 %0, %1, %2, %0;" : "+l"(acc) : "l"(a), "l"(b));
}
__device__ __forceinline__ float lrelu(float x) { return (x > 0.f) ? x : 0.2f * x; }

__device__ __forceinline__ void load_edge(const void* ei, int E, int ec, int& j, int& i) {
    if (g_is64) {
        const long long* p = (const long long*)ei;
        j = (int)p[ec]; i = (int)p[(size_t)E + ec];
    } else {
        const int* p = (const int*)ei;
        j = p[ec]; i = p[(size_t)E + ec];
    }
}

// ---------------- kernel D: detect edge_index dtype ----------------
__global__ void k_detect(const void* ei, int N) {
    const long long* p = (const long long*)ei;
    int ok = 1;
    #pragma unroll 1
    for (int t = 0; t < 64; t++) {
        long long v = p[t];
        if (v < 0 || v >= (long long)N) { ok = 0; break; }
    }
    g_is64 = ok;
}

// ---------------- CSR build ----------------
__global__ void k_zero_deg(int N) {
    int idx = blockIdx.x * blockDim.x + threadIdx.x;
    if (idx < N) g_deg[idx] = 0;
}

__global__ void k_hist(const void* __restrict__ ei, int E, int N) {
    int e = blockIdx.x * blockDim.x + threadIdx.x;
    if (e >= E) return;
    int j, i;
    load_edge(ei, E, e, j, i);
    atomicAdd(&g_deg[i], 1);
}

// --- two-level exclusive scan ---
__global__ void __launch_bounds__(SCAN_BS) kA_scan_local(int N) {
    __shared__ int wt[SCAN_BS / 32];
    const int tid = threadIdx.x, lane = tid & 31, wid = tid >> 5;
    int idx = blockIdx.x * SCAN_BS + tid;
    int v = (idx < N) ? g_deg[idx] : 0;
    int s = v;
    #pragma unroll
    for (int m = 1; m < 32; m <<= 1) {
        int o = __shfl_up_sync(0xffffffffu, s, m);
        if (lane >= m) s += o;
    }
    if (lane == 31) wt[wid] = s;
    __syncthreads();
    if (wid == 0) {
        int w = wt[lane];
        int ws = w;
        #pragma unroll
        for (int m = 1; m < 32; m <<= 1) {
            int o = __shfl_up_sync(0xffffffffu, ws, m);
            if (lane >= m) ws += o;
        }
        wt[lane] = ws - w;   // exclusive warp offsets
    }
    __syncthreads();
    int excl = (s - v) + wt[wid];
    if (idx < N) g_off[idx] = excl;
    if (tid == SCAN_BS - 1) g_blk[blockIdx.x] = excl + v;   // block total
}

__global__ void __launch_bounds__(128) kB_scan_blk(int NB, int N) {
    __shared__ int wt[4];
    const int tid = threadIdx.x, lane = tid & 31, wid = tid >> 5;
    int v = (tid < NB) ? g_blk[tid] : 0;
    int s = v;
    #pragma unroll
    for (int m = 1; m < 32; m <<= 1) {
        int o = __shfl_up_sync(0xffffffffu, s, m);
        if (lane >= m) s += o;
    }
    if (lane == 31) wt[wid] = s;
    __syncthreads();
    if (tid == 0) {
        int c = 0;
        #pragma unroll
        for (int q = 0; q < 4; q++) { int t = wt[q]; wt[q] = c; c += t; }
    }
    __syncthreads();
    int excl = (s - v) + wt[wid];
    if (tid < NB) g_blk[tid] = excl;
    if (tid == NB - 1) g_off[N] = excl + v;
}

__global__ void kC_add(int N) {
    int idx = blockIdx.x * blockDim.x + threadIdx.x;
    if (idx < N) {
        int o = g_off[idx] + g_blk[idx >> 10];
        g_off[idx] = o;
        g_cur[idx] = o;
    }
}

__global__ void k_scatter(const void* __restrict__ ei, int E, int N) {
    int e = blockIdx.x * blockDim.x + threadIdx.x;
    if (e >= E) return;
    int j, i;
    load_edge(ei, E, e, j, i);
    int pos = atomicAdd(&g_cur[i], 1);
    g_src[pos] = j;
}

// ---------------- kernel 1: xlr = fp16( x @ [Wl|Wr] + [bl|br] ) ----------------
__global__ void __launch_bounds__(256) k_gemm(
    const float* __restrict__ x, const float* __restrict__ Wl,
    const float* __restrict__ bl, const float* __restrict__ Wr,
    const float* __restrict__ br, int N)
{
    __shared__ __align__(16) float Xs_t[32][66];   // [kk][m]
    __shared__ __align__(16) float Ws[32][128];    // [kk][n]

    const int tid = threadIdx.x;
    const int tx = tid & 31;
    const int ty = tid >> 5;
    const int m0 = ty * 8;
    const int blockM = blockIdx.x * 64;

    unsigned long long acc[4][4];
    #pragma unroll
    for (int a = 0; a < 4; a++)
        #pragma unroll
        for (int b = 0; b < 4; b++) acc[a][b] = 0ull;

    for (int k0 = 0; k0 < 128; k0 += 32) {
        #pragma unroll
        for (int it = 0; it < 2; it++) {
            int t = tid + it * 256;          // 0..511
            int m = t >> 3;                  // 0..63
            int kkv = (t & 7) * 4;
            int gm = blockM + m;
            float4 v = make_float4(0.f, 0.f, 0.f, 0.f);
            if (gm < N) v = *reinterpret_cast<const float4*>(&x[(size_t)gm * 128 + k0 + kkv]);
            Xs_t[kkv + 0][m] = v.x;
            Xs_t[kkv + 1][m] = v.y;
            Xs_t[kkv + 2][m] = v.z;
            Xs_t[kkv + 3][m] = v.w;
        }
        #pragma unroll
        for (int it = 0; it < 4; it++) {
            int t = tid + it * 256;          // 0..1023
            int kk = t >> 5;                 // 0..31
            int n  = (t & 31) * 4;
            int gk = k0 + kk;
            float4 v = (n < 64)
                ? *reinterpret_cast<const float4*>(&Wl[(size_t)gk * 64 + n])
                : *reinterpret_cast<const float4*>(&Wr[(size_t)gk * 64 + (n - 64)]);
            *reinterpret_cast<float4*>(&Ws[kk][n]) = v;
        }
        __syncthreads();

        #pragma unroll
        for (int kk = 0; kk < 32; kk++) {
            unsigned long long apair[4];
            #pragma unroll
            for (int rp = 0; rp < 4; rp++)
                apair[rp] = *reinterpret_cast<const unsigned long long*>(&Xs_t[kk][m0 + 2 * rp]);
            #pragma unroll
            for (int jj = 0; jj < 4; jj++) {
                unsigned long long wp = pack_dup(Ws[kk][tx + 32 * jj]);
                #pragma unroll
                for (int rp = 0; rp < 4; rp++)
                    fma2(acc[rp][jj], apair[rp], wp);
            }
        }
        __syncthreads();
    }

    #pragma unroll
    for (int jj = 0; jj < 4; jj++) {
        int col = tx + 32 * jj;
        float bsum = (col < HC) ? bl[col] : br[col - HC];
        #pragma unroll
        for (int rp = 0; rp < 4; rp++) {
            float lo, hi;
            unpack2(acc[rp][jj], lo, hi);
            int gm = blockM + m0 + 2 * rp;
            if (gm < N)     g_xlr[(size_t)gm * ROW + col]       = __float2half_rn(lo + bsum);
            if (gm + 1 < N) g_xlr[(size_t)(gm + 1) * ROW + col] = __float2half_rn(hi + bsum);
        }
    }
}

// ---------------- kernel 2: per-node aggregation (warp per dst node, 2 edges/iter) ----------------
// Lane layout: lane&15 covers the full 64-ch row (4 ch/lane); lanes 0-15 = edge A,
// lanes 16-31 = edge B. Within a half-warp: lanes 0-7 head 0, lanes 8-15 head 1.
// Reduction = 3-shfl butterfly over 8-lane groups (serves both edges at once).
__global__ void __launch_bounds__(256) k_agg(
    const float* __restrict__ att, const float* __restrict__ bias,
    float* __restrict__ out, int N)
{
    const int warp = (blockIdx.x * 256 + threadIdx.x) >> 5;
    const int lane = threadIdx.x & 31;
    if (warp >= N) return;
    const int i = warp;

    const int hl = lane & 15;              // position within half-warp
    const int cb = hl * 4;                 // channel base (4 channels), 0..60
    const bool isA = (lane < 16);

    // xr[i] channels cb..cb+3 (8 bytes)
    uint2 bx = *reinterpret_cast<const uint2*>(g_xlr + (size_t)i * ROW + HC + cb);
    float2 b0 = __half22float2(reinterpret_cast<const __half2*>(&bx)[0]);
    float2 b1 = __half22float2(reinterpret_cast<const __half2*>(&bx)[1]);
    float4 t = *reinterpret_cast<const float4*>(&att[cb]);

    float4 acc = make_float4(0.f, 0.f, 0.f, 0.f);
    float d = 0.f;

    // process one edge-pair step; this lane's edge row preloaded in ax, valid flag per lane
    auto proc = [&](uint2 ax, bool valid) {
        float2 a0 = __half22float2(reinterpret_cast<const __half2*>(&ax)[0]);
        float2 a1 = __half22float2(reinterpret_cast<const __half2*>(&ax)[1]);
        float s = t.x * lrelu(a0.x + b0.x) + t.y * lrelu(a0.y + b0.y)
                + t.z * lrelu(a1.x + b1.x) + t.w * lrelu(a1.y + b1.y);
        // butterfly over the 8-lane head group (both edges + both heads in parallel)
        s += __shfl_xor_sync(0xffffffffu, s, 1);
        s += __shfl_xor_sync(0xffffffffu, s, 2);
        s += __shfl_xor_sync(0xffffffffu, s, 4);
        float p = valid ? __expf(s) : 0.f;
        acc.x += p * a0.x; acc.y += p * a0.y;
        acc.z += p * a1.x; acc.w += p * a1.y;
        d += p;
    };

    // self loop (edge A = i, edge B inactive)
    {
        uint2 ax = *reinterpret_cast<const uint2*>(g_xlr + (size_t)i * ROW + cb);
        proc(ax, isA);
    }

    const int off = g_off[i];
    const int deg = g_deg[i];

    for (int tb = 0; tb < deg; tb += 32) {
        int cnt = deg - tb; if (cnt > 32) cnt = 32;
        int mysrc = (tb + lane < deg) ? g_src[off + tb + lane] : 0;

        // preload first pair
        int jA = __shfl_sync(0xffffffffu, mysrc, 0);
        int jB = (cnt > 1) ? __shfl_sync(0xffffffffu, mysrc, 1) : jA;
        int j0 = isA ? jA : jB;
        uint2 vcur = *reinterpret_cast<const uint2*>(g_xlr + (size_t)j0 * ROW + cb);

        for (int u = 0; u < cnt; u += 2) {
            uint2 vnext = vcur;
            bool hasNext = (u + 2 < cnt);
            if (hasNext) {
                int nA = __shfl_sync(0xffffffffu, mysrc, u + 2);
                int nB = (u + 3 < cnt) ? __shfl_sync(0xffffffffu, mysrc, u + 3) : nA;
                int nj = isA ? nA : nB;
                vnext = *reinterpret_cast<const uint2*>(g_xlr + (size_t)nj * ROW + cb);
            }
            bool validB = (u + 1 < cnt);
            proc(vcur, isA || validB);
            vcur = vnext;
        }
    }

    // merge edge streams A/B (xor 16)
    acc.x += __shfl_xor_sync(0xffffffffu, acc.x, 16);
    acc.y += __shfl_xor_sync(0xffffffffu, acc.y, 16);
    acc.z += __shfl_xor_sync(0xffffffffu, acc.z, 16);
    acc.w += __shfl_xor_sync(0xffffffffu, acc.w, 16);
    d     += __shfl_xor_sync(0xffffffffu, d, 16);

    float invd = 1.f / (d + 1e-16f);
    float4 v;
    v.x = acc.x * invd; v.y = acc.y * invd; v.z = acc.z * invd; v.w = acc.w * invd;

    // combine heads (xor 8): lane l (<8) has head0 ch cb..cb+3; lane l+8 has head1 same out ch
    float4 o;
    o.x = 0.5f * (v.x + __shfl_xor_sync(0xffffffffu, v.x, 8));
    o.y = 0.5f * (v.y + __shfl_xor_sync(0xffffffffu, v.y, 8));
    o.z = 0.5f * (v.z + __shfl_xor_sync(0xffffffffu, v.z, 8));
    o.w = 0.5f * (v.w + __shfl_xor_sync(0xffffffffu, v.w, 8));

    if (lane < 8) {
        float4 bi = *reinterpret_cast<const float4*>(&bias[cb]);
        o.x += bi.x; o.y += bi.y; o.z += bi.z; o.w += bi.w;
        o.x = o.x / (1.f + expf(-o.x));
        o.y = o.y / (1.f + expf(-o.y));
        o.z = o.z / (1.f + expf(-o.z));
        o.w = o.w / (1.f + expf(-o.w));
        *reinterpret_cast<float4*>(&out[(size_t)i * OUTC + cb]) = o;
    }
}

// ---------------- launch ----------------
extern "C" void kernel_launch(void* const* d_in, const int* in_sizes, int n_in,
                              void* d_out, int out_size) {
    const float* x    = (const float*)d_in[0];
    const float* Wl   = (const float*)d_in[1];
    const float* bl   = (const float*)d_in[2];
    const float* Wr   = (const float*)d_in[3];
    const float* br   = (const float*)d_in[4];
    const float* att  = (const float*)d_in[5];
    const float* bias = (const float*)d_in[6];
    const void*  ei   = (const void*)d_in[7];
    float* out = (float*)d_out;

    int N = in_sizes[0] / 128;   // 100000
    int E = in_sizes[7] / 2;     // 1600000
    int NB = (N + SCAN_BS - 1) / SCAN_BS;

    k_detect<<<1, 1>>>(ei, N);
    k_zero_deg<<<(N + 255) / 256, 256>>>(N);
    k_hist<<<(E + 255) / 256, 256>>>(ei, E, N);
    kA_scan_local<<<NB, SCAN_BS>>>(N);
    kB_scan_blk<<<1, 128>>>(NB, N);
    kC_add<<<(N + 255) / 256, 256>>>(N);
    k_scatter<<<(E + 255) / 256, 256>>>(ei, E, N);
    k_gemm<<<(N + 63) / 64, 256>>>(x, Wl, bl, Wr, br, N);
    k_agg<<<(N * 32 + 255) / 256, 256>>>(att, bias, out, N);
}

// round 11
// speedup vs baseline: 1.6867x; 1.2594x over previous
#include <cuda_runtime.h>
#include <cuda_fp16.h>
#include <cstdint>

// Problem constants (fixed by the dataset)
#define N_MAX   100000
#define E_MAX   1600000
#define ROW     128        // xl(64) | xr(64) halves per node
#define HC      64         // HEADS * OUT_CH
#define OUTC    32
#define SCAN_BS 1024
#define NBLK_MAX ((N_MAX + SCAN_BS - 1) / SCAN_BS)   // 98

// -------- scratch (static device globals; no allocation) --------
__device__ __align__(128) __half g_xlr[(size_t)N_MAX * ROW];    // 25.6 MB (fp16)
__device__ __align__(128) int   g_deg[N_MAX];
__device__ __align__(128) int   g_off[N_MAX + 1];
__device__ __align__(128) int   g_cur[N_MAX];
__device__ __align__(128) int   g_src[E_MAX];
__device__ __align__(128) int   g_blk[NBLK_MAX + 1];
__device__ int g_is64;   // 1 if edge_index is int64, 0 if int32

// ---------------- helpers ----------------
__device__ __forceinline__ float lrelu(float x) { return (x > 0.f) ? x : 0.2f * x; }

__device__ __forceinline__ uint32_t smem_u32(const void* p) {
    return (uint32_t)__cvta_generic_to_shared(p);
}
__device__ __forceinline__ void ldmatrix_x4(uint32_t& r0, uint32_t& r1, uint32_t& r2, uint32_t& r3, uint32_t addr) {
    asm volatile("ldmatrix.sync.aligned.m8n8.x4.shared.b16 {%0,%1,%2,%3}, [%4];"
                 : "=r"(r0), "=r"(r1), "=r"(r2), "=r"(r3) : "r"(addr));
}
__device__ __forceinline__ void ldmatrix_x4_trans(uint32_t& r0, uint32_t& r1, uint32_t& r2, uint32_t& r3, uint32_t addr) {
    asm volatile("ldmatrix.sync.aligned.m8n8.x4.trans.shared.b16 {%0,%1,%2,%3}, [%4];"
                 : "=r"(r0), "=r"(r1), "=r"(r2), "=r"(r3) : "r"(addr));
}
__device__ __forceinline__ void mma_16816(float* c, uint32_t a0, uint32_t a1, uint32_t a2, uint32_t a3,
                                          uint32_t b0, uint32_t b1) {
    asm volatile("mma.sync.aligned.m16n8k16.row.col.f32.f16.f16.f32 "
                 "{%0,%1,%2,%3},{%4,%5,%6,%7},{%8,%9},{%0,%1,%2,%3};"
                 : "+f"(c[0]), "+f"(c[1]), "+f"(c[2]), "+f"(c[3])
                 : "r"(a0), "r"(a1), "r"(a2), "r"(a3), "r"(b0), "r"(b1));
}

__device__ __forceinline__ void load_edge(const void* ei, int E, int ec, int& j, int& i) {
    if (g_is64) {
        const long long* p = (const long long*)ei;
        j = (int)p[ec]; i = (int)p[(size_t)E + ec];
    } else {
        const int* p = (const int*)ei;
        j = p[ec]; i = p[(size_t)E + ec];
    }
}

// ---------------- kernel D: detect edge_index dtype (1 warp, parallel) ----------------
__global__ void k_detect(const void* ei, int N) {
    const long long* p = (const long long*)ei;
    long long v = p[threadIdx.x];
    bool ok = (v >= 0 && v < (long long)N);
    unsigned m = __ballot_sync(0xffffffffu, ok);
    if (threadIdx.x == 0) g_is64 = (m == 0xffffffffu) ? 1 : 0;
}

// ---------------- CSR build ----------------
__global__ void k_zero_deg(int N) {
    int idx = blockIdx.x * blockDim.x + threadIdx.x;
    if (idx < N) g_deg[idx] = 0;
}

__global__ void k_hist(const void* __restrict__ ei, int E, int N) {
    int e = blockIdx.x * blockDim.x + threadIdx.x;
    if (e >= E) return;
    int j, i;
    load_edge(ei, E, e, j, i);
    atomicAdd(&g_deg[i], 1);
}

// --- two-level exclusive scan ---
__global__ void __launch_bounds__(SCAN_BS) kA_scan_local(int N) {
    __shared__ int wt[SCAN_BS / 32];
    const int tid = threadIdx.x, lane = tid & 31, wid = tid >> 5;
    int idx = blockIdx.x * SCAN_BS + tid;
    int v = (idx < N) ? g_deg[idx] : 0;
    int s = v;
    #pragma unroll
    for (int m = 1; m < 32; m <<= 1) {
        int o = __shfl_up_sync(0xffffffffu, s, m);
        if (lane >= m) s += o;
    }
    if (lane == 31) wt[wid] = s;
    __syncthreads();
    if (wid == 0) {
        int w = wt[lane];
        int ws = w;
        #pragma unroll
        for (int m = 1; m < 32; m <<= 1) {
            int o = __shfl_up_sync(0xffffffffu, ws, m);
            if (lane >= m) ws += o;
        }
        wt[lane] = ws - w;   // exclusive warp offsets
    }
    __syncthreads();
    int excl = (s - v) + wt[wid];
    if (idx < N) g_off[idx] = excl;
    if (tid == SCAN_BS - 1) g_blk[blockIdx.x] = excl + v;   // block total
}

__global__ void __launch_bounds__(128) kB_scan_blk(int NB, int N) {
    __shared__ int wt[4];
    const int tid = threadIdx.x, lane = tid & 31, wid = tid >> 5;
    int v = (tid < NB) ? g_blk[tid] : 0;
    int s = v;
    #pragma unroll
    for (int m = 1; m < 32; m <<= 1) {
        int o = __shfl_up_sync(0xffffffffu, s, m);
        if (lane >= m) s += o;
    }
    if (lane == 31) wt[wid] = s;
    __syncthreads();
    if (tid == 0) {
        int c = 0;
        #pragma unroll
        for (int q = 0; q < 4; q++) { int t = wt[q]; wt[q] = c; c += t; }
    }
    __syncthreads();
    int excl = (s - v) + wt[wid];
    if (tid < NB) g_blk[tid] = excl;
    if (tid == NB - 1) g_off[N] = excl + v;
}

__global__ void kC_add(int N) {
    int idx = blockIdx.x * blockDim.x + threadIdx.x;
    if (idx < N) {
        int o = g_off[idx] + g_blk[idx >> 10];
        g_off[idx] = o;
        g_cur[idx] = o;
    }
}

__global__ void k_scatter(const void* __restrict__ ei, int E, int N) {
    int e = blockIdx.x * blockDim.x + threadIdx.x;
    if (e >= E) return;
    int j, i;
    load_edge(ei, E, e, j, i);
    int pos = atomicAdd(&g_cur[i], 1);
    g_src[pos] = j;
}

// ---------------- kernel 1: tensor-core GEMM -> fp16 xlr ----------------
// BM=128 rows/block, N=128 cols, K chunks of 32. 256 threads = 8 warps.
// Warp w computes rows [16w, 16w+16) x all 128 cols via m16n8k16 fp16 mma.
#define A_STRIDE 40    // halves per row (80B, conflict-free ldmatrix)
#define W_STRIDE 136   // halves per row (272B, conflict-free ldmatrix.trans)
__global__ void __launch_bounds__(256) k_gemm(
    const float* __restrict__ x, const float* __restrict__ Wl,
    const float* __restrict__ bl, const float* __restrict__ Wr,
    const float* __restrict__ br, int N)
{
    __shared__ __align__(16) __half As[128][A_STRIDE];
    __shared__ __align__(16) __half Ws[32][W_STRIDE];
    __shared__ float bcat[128];

    const int tid = threadIdx.x;
    const int warp = tid >> 5;
    const int lane = tid & 31;
    const int blockM = blockIdx.x * 128;

    if (tid < 128) bcat[tid] = (tid < HC) ? bl[tid] : br[tid - HC];

    float acc[16][4];
    #pragma unroll
    for (int nt = 0; nt < 16; nt++)
        #pragma unroll
        for (int q = 0; q < 4; q++) acc[nt][q] = 0.f;

    for (int k0 = 0; k0 < 128; k0 += 32) {
        // x tile: 128 rows x 32 cols, fp32 -> fp16
        #pragma unroll
        for (int it = 0; it < 4; it++) {
            int idx = it * 256 + tid;        // 0..1023
            int row = idx >> 3;              // 0..127
            int c4  = (idx & 7) * 4;         // 0..28
            int gm = blockM + row;
            float4 v = make_float4(0.f, 0.f, 0.f, 0.f);
            if (gm < N) v = *reinterpret_cast<const float4*>(&x[(size_t)gm * 128 + k0 + c4]);
            *reinterpret_cast<__half2*>(&As[row][c4])     = __floats2half2_rn(v.x, v.y);
            *reinterpret_cast<__half2*>(&As[row][c4 + 2]) = __floats2half2_rn(v.z, v.w);
        }
        // W tile: 32 k-rows x 128 cols (Wl | Wr), fp32 -> fp16
        #pragma unroll
        for (int it = 0; it < 4; it++) {
            int idx = it * 256 + tid;        // 0..1023
            int kk = idx >> 5;               // 0..31
            int c4 = (idx & 31) * 4;         // 0..124
            int gk = k0 + kk;
            float4 v = (c4 < HC)
                ? *reinterpret_cast<const float4*>(&Wl[(size_t)gk * HC + c4])
                : *reinterpret_cast<const float4*>(&Wr[(size_t)gk * HC + (c4 - HC)]);
            *reinterpret_cast<__half2*>(&Ws[kk][c4])     = __floats2half2_rn(v.x, v.y);
            *reinterpret_cast<__half2*>(&Ws[kk][c4 + 2]) = __floats2half2_rn(v.z, v.w);
        }
        __syncthreads();

        #pragma unroll
        for (int ks = 0; ks < 32; ks += 16) {
            uint32_t a0, a1, a2, a3;
            {
                int g = lane >> 3, r = lane & 7;
                int arow = warp * 16 + ((g & 1) ? 8 : 0) + r;
                int acol = ks + ((g & 2) ? 8 : 0);
                ldmatrix_x4(a0, a1, a2, a3, smem_u32(&As[arow][acol]));
            }
            #pragma unroll
            for (int p = 0; p < 8; p++) {
                int g = lane >> 3, r = lane & 7;
                int krow = ks + ((g & 1) ? 8 : 0) + r;
                int ncol = p * 16 + ((g & 2) ? 8 : 0);
                uint32_t b0, b1, b2, b3;
                ldmatrix_x4_trans(b0, b1, b2, b3, smem_u32(&Ws[krow][ncol]));
                mma_16816(acc[2 * p],     a0, a1, a2, a3, b0, b1);
                mma_16816(acc[2 * p + 1], a0, a1, a2, a3, b2, b3);
            }
        }
        __syncthreads();
    }

    // epilogue: bias + fp16 store
    const int crow0 = blockM + warp * 16 + (lane >> 2);
    const int ccol0 = 2 * (lane & 3);
    #pragma unroll
    for (int nt = 0; nt < 16; nt++) {
        int col = nt * 8 + ccol0;
        float bx = bcat[col], by = bcat[col + 1];
        if (crow0 < N)
            *reinterpret_cast<__half2*>(&g_xlr[(size_t)crow0 * ROW + col]) =
                __floats2half2_rn(acc[nt][0] + bx, acc[nt][1] + by);
        if (crow0 + 8 < N)
            *reinterpret_cast<__half2*>(&g_xlr[(size_t)(crow0 + 8) * ROW + col]) =
                __floats2half2_rn(acc[nt][2] + bx, acc[nt][3] + by);
    }
}

// ---------------- kernel 2: per-node aggregation (warp per dst node, 2 edges/iter) ----------------
__global__ void __launch_bounds__(256) k_agg(
    const float* __restrict__ att, const float* __restrict__ bias,
    float* __restrict__ out, int N)
{
    const int warp = (blockIdx.x * 256 + threadIdx.x) >> 5;
    const int lane = threadIdx.x & 31;
    if (warp >= N) return;
    const int i = warp;

    const int hl = lane & 15;
    const int cb = hl * 4;
    const bool isA = (lane < 16);

    uint2 bx = *reinterpret_cast<const uint2*>(g_xlr + (size_t)i * ROW + HC + cb);
    float2 b0 = __half22float2(reinterpret_cast<const __half2*>(&bx)[0]);
    float2 b1 = __half22float2(reinterpret_cast<const __half2*>(&bx)[1]);
    float4 t = *reinterpret_cast<const float4*>(&att[cb]);

    float4 acc = make_float4(0.f, 0.f, 0.f, 0.f);
    float d = 0.f;

    auto proc = [&](uint2 ax, bool valid) {
        float2 a0 = __half22float2(reinterpret_cast<const __half2*>(&ax)[0]);
        float2 a1 = __half22float2(reinterpret_cast<const __half2*>(&ax)[1]);
        float s = t.x * lrelu(a0.x + b0.x) + t.y * lrelu(a0.y + b0.y)
                + t.z * lrelu(a1.x + b1.x) + t.w * lrelu(a1.y + b1.y);
        s += __shfl_xor_sync(0xffffffffu, s, 1);
        s += __shfl_xor_sync(0xffffffffu, s, 2);
        s += __shfl_xor_sync(0xffffffffu, s, 4);
        float p = valid ? __expf(s) : 0.f;
        acc.x += p * a0.x; acc.y += p * a0.y;
        acc.z += p * a1.x; acc.w += p * a1.y;
        d += p;
    };

    {
        uint2 ax = *reinterpret_cast<const uint2*>(g_xlr + (size_t)i * ROW + cb);
        proc(ax, isA);
    }

    const int off = g_off[i];
    const int deg = g_deg[i];

    for (int tb = 0; tb < deg; tb += 32) {
        int cnt = deg - tb; if (cnt > 32) cnt = 32;
        int mysrc = (tb + lane < deg) ? g_src[off + tb + lane] : 0;

        int jA = __shfl_sync(0xffffffffu, mysrc, 0);
        int jB = (cnt > 1) ? __shfl_sync(0xffffffffu, mysrc, 1) : jA;
        int j0 = isA ? jA : jB;
        uint2 vcur = *reinterpret_cast<const uint2*>(g_xlr + (size_t)j0 * ROW + cb);

        for (int u = 0; u < cnt; u += 2) {
            uint2 vnext = vcur;
            bool hasNext = (u + 2 < cnt);
            if (hasNext) {
                int nA = __shfl_sync(0xffffffffu, mysrc, u + 2);
                int nB = (u + 3 < cnt) ? __shfl_sync(0xffffffffu, mysrc, u + 3) : nA;
                int nj = isA ? nA : nB;
                vnext = *reinterpret_cast<const uint2*>(g_xlr + (size_t)nj * ROW + cb);
            }
            bool validB = (u + 1 < cnt);
            proc(vcur, isA || validB);
            vcur = vnext;
        }
    }

    acc.x += __shfl_xor_sync(0xffffffffu, acc.x, 16);
    acc.y += __shfl_xor_sync(0xffffffffu, acc.y, 16);
    acc.z += __shfl_xor_sync(0xffffffffu, acc.z, 16);
    acc.w += __shfl_xor_sync(0xffffffffu, acc.w, 16);
    d     += __shfl_xor_sync(0xffffffffu, d, 16);

    float invd = 1.f / (d + 1e-16f);
    float4 v;
    v.x = acc.x * invd; v.y = acc.y * invd; v.z = acc.z * invd; v.w = acc.w * invd;

    float4 o;
    o.x = 0.5f * (v.x + __shfl_xor_sync(0xffffffffu, v.x, 8));
    o.y = 0.5f * (v.y + __shfl_xor_sync(0xffffffffu, v.y, 8));
    o.z = 0.5f * (v.z + __shfl_xor_sync(0xffffffffu, v.z, 8));
    o.w = 0.5f * (v.w + __shfl_xor_sync(0xffffffffu, v.w, 8));

    if (lane < 8) {
        float4 bi = *reinterpret_cast<const float4*>(&bias[cb]);
        o.x += bi.x; o.y += bi.y; o.z += bi.z; o.w += bi.w;
        o.x = o.x / (1.f + expf(-o.x));
        o.y = o.y / (1.f + expf(-o.y));
        o.z = o.z / (1.f + expf(-o.z));
        o.w = o.w / (1.f + expf(-o.w));
        *reinterpret_cast<float4*>(&out[(size_t)i * OUTC + cb]) = o;
    }
}

// ---------------- launch ----------------
extern "C" void kernel_launch(void* const* d_in, const int* in_sizes, int n_in,
                              void* d_out, int out_size) {
    const float* x    = (const float*)d_in[0];
    const float* Wl   = (const float*)d_in[1];
    const float* bl   = (const float*)d_in[2];
    const float* Wr   = (const float*)d_in[3];
    const float* br   = (const float*)d_in[4];
    const float* att  = (const float*)d_in[5];
    const float* bias = (const float*)d_in[6];
    const void*  ei   = (const void*)d_in[7];
    float* out = (float*)d_out;

    int N = in_sizes[0] / 128;   // 100000
    int E = in_sizes[7] / 2;     // 1600000
    int NB = (N + SCAN_BS - 1) / SCAN_BS;

    k_detect<<<1, 32>>>(ei, N);
    k_zero_deg<<<(N + 255) / 256, 256>>>(N);
    k_hist<<<(E + 255) / 256, 256>>>(ei, E, N);
    kA_scan_local<<<NB, SCAN_BS>>>(N);
    kB_scan_blk<<<1, 128>>>(NB, N);
    kC_add<<<(N + 255) / 256, 256>>>(N);
    k_scatter<<<(E + 255) / 256, 256>>>(ei, E, N);
    k_gemm<<<(N + 127) / 128, 256>>>(x, Wl, bl, Wr, br, N);
    k_agg<<<(N * 32 + 255) / 256, 256>>>(att, bias, out, N);
}

// round 13
// speedup vs baseline: 1.7284x; 1.0247x over previous
#include <cuda_runtime.h>
#include <cuda_fp16.h>
#include <cstdint>

// Problem constants (fixed by the dataset)
#define N_MAX   100000
#define E_MAX   1600000
#define ROW     128        // xl(64) | xr(64) halves per node
#define HC      64         // HEADS * OUT_CH
#define OUTC    32
#define SCAN_BS 1024
#define NBLK_MAX ((N_MAX + SCAN_BS - 1) / SCAN_BS)   // 98

// -------- scratch (static device globals; no allocation) --------
__device__ __align__(128) __half g_xlr[(size_t)N_MAX * ROW];    // 25.6 MB (fp16)
__device__ __align__(128) int   g_deg[N_MAX];
__device__ __align__(128) int   g_off[N_MAX + 1];
__device__ __align__(128) int   g_cur[N_MAX];
__device__ __align__(128) int   g_src[E_MAX];
__device__ __align__(128) int   g_blk[NBLK_MAX + 1];
__device__ int g_is64;   // 1 if edge_index is int64, 0 if int32

// ---------------- helpers ----------------
__device__ __forceinline__ float lrelu(float x) { return (x > 0.f) ? x : 0.2f * x; }

__device__ __forceinline__ uint32_t smem_u32(const void* p) {
    return (uint32_t)__cvta_generic_to_shared(p);
}
__device__ __forceinline__ void ldmatrix_x4(uint32_t& r0, uint32_t& r1, uint32_t& r2, uint32_t& r3, uint32_t addr) {
    asm volatile("ldmatrix.sync.aligned.m8n8.x4.shared.b16 {%0,%1,%2,%3}, [%4];"
                 : "=r"(r0), "=r"(r1), "=r"(r2), "=r"(r3) : "r"(addr));
}
__device__ __forceinline__ void ldmatrix_x4_trans(uint32_t& r0, uint32_t& r1, uint32_t& r2, uint32_t& r3, uint32_t addr) {
    asm volatile("ldmatrix.sync.aligned.m8n8.x4.trans.shared.b16 {%0,%1,%2,%3}, [%4];"
                 : "=r"(r0), "=r"(r1), "=r"(r2), "=r"(r3) : "r"(addr));
}
__device__ __forceinline__ void mma_16816(float* c, uint32_t a0, uint32_t a1, uint32_t a2, uint32_t a3,
                                          uint32_t b0, uint32_t b1) {
    asm volatile("mma.sync.aligned.m16n8k16.row.col.f32.f16.f16.f32 "
                 "{%0,%1,%2,%3},{%4,%5,%6,%7},{%8,%9},{%0,%1,%2,%3};"
                 : "+f"(c[0]), "+f"(c[1]), "+f"(c[2]), "+f"(c[3])
                 : "r"(a0), "r"(a1), "r"(a2), "r"(a3), "r"(b0), "r"(b1));
}

__device__ __forceinline__ void load_edge(const void* ei, int E, int ec, int& j, int& i) {
    if (g_is64) {
        const long long* p = (const long long*)ei;
        j = (int)p[ec]; i = (int)p[(size_t)E + ec];
    } else {
        const int* p = (const int*)ei;
        j = p[ec]; i = p[(size_t)E + ec];
    }
}

// ---------------- kernel 0: fused detect-dtype + zero degrees ----------------
__global__ void k_init(const void* ei, int N) {
    int idx = blockIdx.x * blockDim.x + threadIdx.x;
    if (idx < N) g_deg[idx] = 0;
    if (blockIdx.x == 0 && threadIdx.x < 32) {
        const long long* p = (const long long*)ei;
        long long v = p[threadIdx.x];
        bool ok = (v >= 0 && v < (long long)N);
        unsigned m = __ballot_sync(0xffffffffu, ok);
        if (threadIdx.x == 0) g_is64 = (m == 0xffffffffu) ? 1 : 0;
    }
}

// ---------------- kernel 1: FUSED tensor-core GEMM + edge histogram ----------------
// Blocks [0, GB): GEMM tile (128 rows x 128 cols via m16n8k16 fp16 mma).
// Blocks [GB, GB+HB): histogram 1024 edges each into g_deg.
// The two roles are data-independent; the GPU co-schedules them (stream-free overlap).
#define A_STRIDE 40    // halves per row (80B, conflict-free ldmatrix)
#define W_STRIDE 136   // halves per row (272B, conflict-free ldmatrix.trans)
__global__ void __launch_bounds__(256) k_gemm_hist(
    const float* __restrict__ x, const float* __restrict__ Wl,
    const float* __restrict__ bl, const float* __restrict__ Wr,
    const float* __restrict__ br, const void* __restrict__ ei,
    int N, int E, int GB)
{
    if (blockIdx.x >= GB) {
        // ---- histogram role ----
        int base = (blockIdx.x - GB) * 1024 + threadIdx.x;
        #pragma unroll
        for (int q = 0; q < 4; q++) {
            int e = base + q * 256;
            if (e < E) {
                int j, i;
                load_edge(ei, E, e, j, i);
                atomicAdd(&g_deg[i], 1);
            }
        }
        return;
    }

    // ---- GEMM role ----
    __shared__ __align__(16) __half As[128][A_STRIDE];
    __shared__ __align__(16) __half Ws[32][W_STRIDE];
    __shared__ float bcat[128];

    const int tid = threadIdx.x;
    const int warp = tid >> 5;
    const int lane = tid & 31;
    const int blockM = blockIdx.x * 128;

    if (tid < 128) bcat[tid] = (tid < HC) ? bl[tid] : br[tid - HC];

    float acc[16][4];
    #pragma unroll
    for (int nt = 0; nt < 16; nt++)
        #pragma unroll
        for (int q = 0; q < 4; q++) acc[nt][q] = 0.f;

    for (int k0 = 0; k0 < 128; k0 += 32) {
        #pragma unroll
        for (int it = 0; it < 4; it++) {
            int idx = it * 256 + tid;        // 0..1023
            int row = idx >> 3;              // 0..127
            int c4  = (idx & 7) * 4;         // 0..28
            int gm = blockM + row;
            float4 v = make_float4(0.f, 0.f, 0.f, 0.f);
            if (gm < N) v = *reinterpret_cast<const float4*>(&x[(size_t)gm * 128 + k0 + c4]);
            *reinterpret_cast<__half2*>(&As[row][c4])     = __floats2half2_rn(v.x, v.y);
            *reinterpret_cast<__half2*>(&As[row][c4 + 2]) = __floats2half2_rn(v.z, v.w);
        }
        #pragma unroll
        for (int it = 0; it < 4; it++) {
            int idx = it * 256 + tid;        // 0..1023
            int kk = idx >> 5;               // 0..31
            int c4 = (idx & 31) * 4;         // 0..124
            int gk = k0 + kk;
            float4 v = (c4 < HC)
                ? *reinterpret_cast<const float4*>(&Wl[(size_t)gk * HC + c4])
                : *reinterpret_cast<const float4*>(&Wr[(size_t)gk * HC + (c4 - HC)]);
            *reinterpret_cast<__half2*>(&Ws[kk][c4])     = __floats2half2_rn(v.x, v.y);
            *reinterpret_cast<__half2*>(&Ws[kk][c4 + 2]) = __floats2half2_rn(v.z, v.w);
        }
        __syncthreads();

        #pragma unroll
        for (int ks = 0; ks < 32; ks += 16) {
            uint32_t a0, a1, a2, a3;
            {
                int g = lane >> 3, r = lane & 7;
                int arow = warp * 16 + ((g & 1) ? 8 : 0) + r;
                int acol = ks + ((g & 2) ? 8 : 0);
                ldmatrix_x4(a0, a1, a2, a3, smem_u32(&As[arow][acol]));
            }
            #pragma unroll
            for (int p = 0; p < 8; p++) {
                int g = lane >> 3, r = lane & 7;
                int krow = ks + ((g & 1) ? 8 : 0) + r;
                int ncol = p * 16 + ((g & 2) ? 8 : 0);
                uint32_t b0, b1, b2, b3;
                ldmatrix_x4_trans(b0, b1, b2, b3, smem_u32(&Ws[krow][ncol]));
                mma_16816(acc[2 * p],     a0, a1, a2, a3, b0, b1);
                mma_16816(acc[2 * p + 1], a0, a1, a2, a3, b2, b3);
            }
        }
        __syncthreads();
    }

    const int crow0 = blockM + warp * 16 + (lane >> 2);
    const int ccol0 = 2 * (lane & 3);
    #pragma unroll
    for (int nt = 0; nt < 16; nt++) {
        int col = nt * 8 + ccol0;
        float bx = bcat[col], by = bcat[col + 1];
        if (crow0 < N)
            *reinterpret_cast<__half2*>(&g_xlr[(size_t)crow0 * ROW + col]) =
                __floats2half2_rn(acc[nt][0] + bx, acc[nt][1] + by);
        if (crow0 + 8 < N)
            *reinterpret_cast<__half2*>(&g_xlr[(size_t)(crow0 + 8) * ROW + col]) =
                __floats2half2_rn(acc[nt][2] + bx, acc[nt][3] + by);
    }
}

// --- two-level exclusive scan ---
__global__ void __launch_bounds__(SCAN_BS) kA_scan_local(int N) {
    __shared__ int wt[SCAN_BS / 32];
    const int tid = threadIdx.x, lane = tid & 31, wid = tid >> 5;
    int idx = blockIdx.x * SCAN_BS + tid;
    int v = (idx < N) ? g_deg[idx] : 0;
    int s = v;
    #pragma unroll
    for (int m = 1; m < 32; m <<= 1) {
        int o = __shfl_up_sync(0xffffffffu, s, m);
        if (lane >= m) s += o;
    }
    if (lane == 31) wt[wid] = s;
    __syncthreads();
    if (wid == 0) {
        int w = wt[lane];
        int ws = w;
        #pragma unroll
        for (int m = 1; m < 32; m <<= 1) {
            int o = __shfl_up_sync(0xffffffffu, ws, m);
            if (lane >= m) ws += o;
        }
        wt[lane] = ws - w;   // exclusive warp offsets
    }
    __syncthreads();
    int excl = (s - v) + wt[wid];
    if (idx < N) g_off[idx] = excl;
    if (tid == SCAN_BS - 1) g_blk[blockIdx.x] = excl + v;   // block total
}

__global__ void __launch_bounds__(128) kB_scan_blk(int NB, int N) {
    __shared__ int wt[4];
    const int tid = threadIdx.x, lane = tid & 31, wid = tid >> 5;
    int v = (tid < NB) ? g_blk[tid] : 0;
    int s = v;
    #pragma unroll
    for (int m = 1; m < 32; m <<= 1) {
        int o = __shfl_up_sync(0xffffffffu, s, m);
        if (lane >= m) s += o;
    }
    if (lane == 31) wt[wid] = s;
    __syncthreads();
    if (tid == 0) {
        int c = 0;
        #pragma unroll
        for (int q = 0; q < 4; q++) { int t = wt[q]; wt[q] = c; c += t; }
    }
    __syncthreads();
    int excl = (s - v) + wt[wid];
    if (tid < NB) g_blk[tid] = excl;
    if (tid == NB - 1) g_off[N] = excl + v;
}

__global__ void kC_add(int N) {
    int idx = blockIdx.x * blockDim.x + threadIdx.x;
    if (idx < N) {
        int o = g_off[idx] + g_blk[idx >> 10];
        g_off[idx] = o;
        g_cur[idx] = o;
    }
}

__global__ void k_scatter(const void* __restrict__ ei, int E, int N) {
    int e = blockIdx.x * blockDim.x + threadIdx.x;
    if (e >= E) return;
    int j, i;
    load_edge(ei, E, e, j, i);
    int pos = atomicAdd(&g_cur[i], 1);
    g_src[pos] = j;
}

// ---------------- kernel 2: per-node aggregation (warp per dst node, 2 edges/iter) ----------------
__global__ void __launch_bounds__(256) k_agg(
    const float* __restrict__ att, const float* __restrict__ bias,
    float* __restrict__ out, int N)
{
    const int warp = (blockIdx.x * 256 + threadIdx.x) >> 5;
    const int lane = threadIdx.x & 31;
    if (warp >= N) return;
    const int i = warp;

    const int hl = lane & 15;
    const int cb = hl * 4;
    const bool isA = (lane < 16);

    uint2 bx = *reinterpret_cast<const uint2*>(g_xlr + (size_t)i * ROW + HC + cb);
    float2 b0 = __half22float2(reinterpret_cast<const __half2*>(&bx)[0]);
    float2 b1 = __half22float2(reinterpret_cast<const __half2*>(&bx)[1]);
    float4 t = *reinterpret_cast<const float4*>(&att[cb]);

    float4 acc = make_float4(0.f, 0.f, 0.f, 0.f);
    float d = 0.f;

    auto proc = [&](uint2 ax, bool valid) {
        float2 a0 = __half22float2(reinterpret_cast<const __half2*>(&ax)[0]);
        float2 a1 = __half22float2(reinterpret_cast<const __half2*>(&ax)[1]);
        float s = t.x * lrelu(a0.x + b0.x) + t.y * lrelu(a0.y + b0.y)
                + t.z * lrelu(a1.x + b1.x) + t.w * lrelu(a1.y + b1.y);
        s += __shfl_xor_sync(0xffffffffu, s, 1);
        s += __shfl_xor_sync(0xffffffffu, s, 2);
        s += __shfl_xor_sync(0xffffffffu, s, 4);
        float p = valid ? __expf(s) : 0.f;
        acc.x += p * a0.x; acc.y += p * a0.y;
        acc.z += p * a1.x; acc.w += p * a1.y;
        d += p;
    };

    {
        uint2 ax = *reinterpret_cast<const uint2*>(g_xlr + (size_t)i * ROW + cb);
        proc(ax, isA);
    }

    const int off = g_off[i];
    const int deg = g_deg[i];

    for (int tb = 0; tb < deg; tb += 32) {
        int cnt = deg - tb; if (cnt > 32) cnt = 32;
        int mysrc = (tb + lane < deg) ? g_src[off + tb + lane] : 0;

        int jA = __shfl_sync(0xffffffffu, mysrc, 0);
        int jB = (cnt > 1) ? __shfl_sync(0xffffffffu, mysrc, 1) : jA;
        int j0 = isA ? jA : jB;
        uint2 vcur = *reinterpret_cast<const uint2*>(g_xlr + (size_t)j0 * ROW + cb);

        for (int u = 0; u < cnt; u += 2) {
            uint2 vnext = vcur;
            bool hasNext = (u + 2 < cnt);
            if (hasNext) {
                int nA = __shfl_sync(0xffffffffu, mysrc, u + 2);
                int nB = (u + 3 < cnt) ? __shfl_sync(0xffffffffu, mysrc, u + 3) : nA;
                int nj = isA ? nA : nB;
                vnext = *reinterpret_cast<const uint2*>(g_xlr + (size_t)nj * ROW + cb);
            }
            bool validB = (u + 1 < cnt);
            proc(vcur, isA || validB);
            vcur = vnext;
        }
    }

    acc.x += __shfl_xor_sync(0xffffffffu, acc.x, 16);
    acc.y += __shfl_xor_sync(0xffffffffu, acc.y, 16);
    acc.z += __shfl_xor_sync(0xffffffffu, acc.z, 16);
    acc.w += __shfl_xor_sync(0xffffffffu, acc.w, 16);
    d     += __shfl_xor_sync(0xffffffffu, d, 16);

    float invd = 1.f / (d + 1e-16f);
    float4 v;
    v.x = acc.x * invd; v.y = acc.y * invd; v.z = acc.z * invd; v.w = acc.w * invd;

    float4 o;
    o.x = 0.5f * (v.x + __shfl_xor_sync(0xffffffffu, v.x, 8));
    o.y = 0.5f * (v.y + __shfl_xor_sync(0xffffffffu, v.y, 8));
    o.z = 0.5f * (v.z + __shfl_xor_sync(0xffffffffu, v.z, 8));
    o.w = 0.5f * (v.w + __shfl_xor_sync(0xffffffffu, v.w, 8));

    if (lane < 8) {
        float4 bi = *reinterpret_cast<const float4*>(&bias[cb]);
        o.x += bi.x; o.y += bi.y; o.z += bi.z; o.w += bi.w;
        o.x = o.x / (1.f + expf(-o.x));
        o.y = o.y / (1.f + expf(-o.y));
        o.z = o.z / (1.f + expf(-o.z));
        o.w = o.w / (1.f + expf(-o.w));
        *reinterpret_cast<float4*>(&out[(size_t)i * OUTC + cb]) = o;
    }
}

// ---------------- launch ----------------
extern "C" void kernel_launch(void* const* d_in, const int* in_sizes, int n_in,
                              void* d_out, int out_size) {
    const float* x    = (const float*)d_in[0];
    const float* Wl   = (const float*)d_in[1];
    const float* bl   = (const float*)d_in[2];
    const float* Wr   = (const float*)d_in[3];
    const float* br   = (const float*)d_in[4];
    const float* att  = (const float*)d_in[5];
    const float* bias = (const float*)d_in[6];
    const void*  ei   = (const void*)d_in[7];
    float* out = (float*)d_out;

    int N = in_sizes[0] / 128;   // 100000
    int E = in_sizes[7] / 2;     // 1600000
    int NB = (N + SCAN_BS - 1) / SCAN_BS;
    int GB = (N + 127) / 128;            // GEMM blocks
    int HB = (E + 1023) / 1024;          // histogram blocks

    k_init<<<(N + 255) / 256, 256>>>(ei, N);
    k_gemm_hist<<<GB + HB, 256>>>(x, Wl, bl, Wr, br, ei, N, E, GB);
    kA_scan_local<<<NB, SCAN_BS>>>(N);
    kB_scan_blk<<<1, 128>>>(NB, N);
    kC_add<<<(N + 255) / 256, 256>>>(N);
    k_scatter<<<(E + 255) / 256, 256>>>(ei, E, N);
    k_agg<<<(N * 32 + 255) / 256, 256>>>(att, bias, out, N);
}